// round 4
// baseline (speedup 1.0000x reference)
#include <cuda_runtime.h>
#include <math.h>

#define JJ   20
#define NH   16
#define NSEQ 8192
#define NB   8
#define HD4  16          // float4 per 64-float row
#define P    8           // positions per 8-lane group (per phase)
#define GROUPS 32        // 256 threads / 8 lanes
#define POS_PER_CTA 256  // GROUPS * P

// ---- packed f32x2 helpers (sm_103a) ----
struct f2 { unsigned long long u; };
__device__ __forceinline__ f2 fpack(float x, float y) {
    f2 r; asm("mov.b64 %0, {%1,%2};" : "=l"(r.u) : "f"(x), "f"(y)); return r;
}
__device__ __forceinline__ f2 ffma2(f2 a, f2 b, f2 c) {
    f2 r; asm("fma.rn.f32x2 %0, %1, %2, %3;" : "=l"(r.u) : "l"(a.u), "l"(b.u), "l"(c.u)); return r;
}
__device__ __forceinline__ f2 fmul2(f2 a, f2 b) {
    f2 r; asm("mul.rn.f32x2 %0, %1, %2;" : "=l"(r.u) : "l"(a.u), "l"(b.u)); return r;
}
__device__ __forceinline__ void funpack(f2 a, float& x, float& y) {
    asm("mov.b64 {%0,%1}, %2;" : "=f"(x), "=f"(y) : "l"(a.u));
}

__global__ __launch_bounds__(256, 2)
void dsqg_attn_kernel(const float* __restrict__ q,
                      const float* __restrict__ k,
                      const float* __restrict__ v,
                      const float* __restrict__ pos_bias,     // [J, H]
                      const float* __restrict__ scale_embed,  // [J, HD]
                      float* __restrict__ out)
{
    const int OFFS[JJ] = {1,2,3,4,5,6,7,8,9,11,13,15,16,23,32,64,128,256,512,1024};

    __shared__ float4 s_se[JJ][HD4];        // 5 KB
    __shared__ float  s_pb[JJ];
    __shared__ float  s_e[POS_PER_CTA * 21]; // stride 21 -> conflict-free (21*8 mod 32 = 8)

    const int blocks_per_seq = NSEQ / POS_PER_CTA;          // 32
    const int bh   = blockIdx.x / blocks_per_seq;           // 0..127
    const int seq0 = (blockIdx.x % blocks_per_seq) * POS_PER_CTA;
    const int h    = bh % NH;

    for (int i = threadIdx.x; i < JJ * HD4; i += 256)
        ((float4*)s_se)[i] = ((const float4*)scale_embed)[i];
    if (threadIdx.x < JJ)
        s_pb[threadIdx.x] = pos_bias[threadIdx.x * NH + h];
    __syncthreads();

    const int gid  = threadIdx.x >> 3;     // 0..31
    const int lane = threadIdx.x & 7;      // 0..7
    const int n0   = seq0 + gid * P;
    const int ebase = (gid * P) * 21;

    const size_t bh_row0 = (size_t)bh * NSEQ * HD4;
    const float4* __restrict__ kb4 = (const float4*)k + bh_row0;
    const float4* __restrict__ vb4 = (const float4*)v + bh_row0;
    const float4* __restrict__ qb4 = (const float4*)q + bh_row0;

    const float sc = 0.125f;

    // ================= PHASE 1: scores -> exp -> smem =================
    {
        f2 qv[P][4];
        float denom_[P];
        #pragma unroll
        for (int p = 0; p < P; p++) {
            const float4* qr = qb4 + (size_t)(n0 + p) * HD4;
            float4 a = qr[lane], b = qr[lane + 8];
            qv[p][0] = fpack(a.x * sc, a.y * sc);
            qv[p][1] = fpack(a.z * sc, a.w * sc);
            qv[p][2] = fpack(b.x * sc, b.y * sc);
            qv[p][3] = fpack(b.z * sc, b.w * sc);
            denom_[p] = 0.f;
        }

        auto pair1 = [&](int j, int p, f2 k0, f2 k1, f2 k2, f2 k3, bool valid) {
            float4 sa = s_se[j][lane];
            float4 sb = s_se[j][lane + 8];
            f2 a = fmul2(qv[p][0], k0);
            a = ffma2(qv[p][1], k1, a);
            a = ffma2(qv[p][2], k2, a);
            a = ffma2(qv[p][3], k3, a);
            a = ffma2(qv[p][0], fpack(sa.x, sa.y), a);
            a = ffma2(qv[p][1], fpack(sa.z, sa.w), a);
            a = ffma2(qv[p][2], fpack(sb.x, sb.y), a);
            a = ffma2(qv[p][3], fpack(sb.z, sb.w), a);
            float px, py; funpack(a, px, py);
            float part = px + py;
            part += __shfl_xor_sync(0xffffffffu, part, 4);
            part += __shfl_xor_sync(0xffffffffu, part, 2);
            part += __shfl_xor_sync(0xffffffffu, part, 1);
            // No max-subtraction: scores are O(+-8), far below fp32 exp range.
            float e = valid ? __expf(part + s_pb[j]) : 0.f;
            denom_[p] += e;
            if (lane == 0) s_e[ebase + p * 21 + j] = e;
        };

        // dense window t in [-23, 6]: covers offsets 1..23 (j = 0..13)
        #pragma unroll
        for (int i = 0; i < 30; i++) {
            const int t = i - 23;
            const int r = n0 + t;
            const bool valid = (r >= 0);
            const int rc = valid ? r : 0;
            const float4* kr = kb4 + (size_t)rc * HD4;
            float4 ka = kr[lane], kb2 = kr[lane + 8];
            f2 k0 = fpack(ka.x, ka.y), k1 = fpack(ka.z, ka.w);
            f2 k2 = fpack(kb2.x, kb2.y), k3 = fpack(kb2.z, kb2.w);
            #pragma unroll
            for (int j = 0; j < 14; j++) {
                const int p = t + OFFS[j];
                if (p >= 0 && p < P) pair1(j, p, k0, k1, k2, k3, valid);
            }
        }
        // isolated offsets 32..1024 (j = 14..19): one pair per row
        #pragma unroll
        for (int j = 14; j < JJ; j++) {
            const int d = OFFS[j];
            #pragma unroll
            for (int u = 0; u < P; u++) {
                const int r = n0 + u - d;
                const bool valid = (r >= 0);
                const int rc = valid ? r : 0;
                const float4* kr = kb4 + (size_t)rc * HD4;
                float4 ka = kr[lane], kb2 = kr[lane + 8];
                pair1(j, u,
                      fpack(ka.x, ka.y), fpack(ka.z, ka.w),
                      fpack(kb2.x, kb2.y), fpack(kb2.z, kb2.w), valid);
            }
        }

        // stash inv-denominators in smem slot j=20 of each position
        #pragma unroll
        for (int p = 0; p < P; p++) {
            if (lane == 0) s_e[ebase + p * 21 + 20] = 1.0f / fmaxf(denom_[p], 1e-30f);
        }
    }

    __syncwarp();   // e produced/consumed within the same warp

    // ================= PHASE 2: out = sum_j e * v =================
    {
        f2 oacc[P][4];
        #pragma unroll
        for (int p = 0; p < P; p++)
            #pragma unroll
            for (int c = 0; c < 4; c++) oacc[p][c] = fpack(0.f, 0.f);

        auto pair2 = [&](int j, int p, f2 v0, f2 v1, f2 v2, f2 v3) {
            float e = s_e[ebase + p * 21 + j];
            f2 e2 = fpack(e, e);
            oacc[p][0] = ffma2(e2, v0, oacc[p][0]);
            oacc[p][1] = ffma2(e2, v1, oacc[p][1]);
            oacc[p][2] = ffma2(e2, v2, oacc[p][2]);
            oacc[p][3] = ffma2(e2, v3, oacc[p][3]);
        };

        #pragma unroll
        for (int i = 0; i < 30; i++) {
            const int t = i - 23;
            const int r = n0 + t;
            const int rc = (r >= 0) ? r : 0;   // e==0 when masked, clamp safe
            const float4* vr = vb4 + (size_t)rc * HD4;
            float4 va = vr[lane], vb2 = vr[lane + 8];
            f2 v0 = fpack(va.x, va.y), v1 = fpack(va.z, va.w);
            f2 v2 = fpack(vb2.x, vb2.y), v3 = fpack(vb2.z, vb2.w);
            #pragma unroll
            for (int j = 0; j < 14; j++) {
                const int p = t + OFFS[j];
                if (p >= 0 && p < P) pair2(j, p, v0, v1, v2, v3);
            }
        }
        #pragma unroll
        for (int j = 14; j < JJ; j++) {
            const int d = OFFS[j];
            #pragma unroll
            for (int u = 0; u < P; u++) {
                const int r = n0 + u - d;
                const int rc = (r >= 0) ? r : 0;
                const float4* vr = vb4 + (size_t)rc * HD4;
                float4 va = vr[lane], vb2 = vr[lane + 8];
                pair2(j, u,
                      fpack(va.x, va.y), fpack(va.z, va.w),
                      fpack(vb2.x, vb2.y), fpack(vb2.z, vb2.w));
            }
        }

        // normalize + store
        #pragma unroll
        for (int p = 0; p < P; p++) {
            const float inv = s_e[ebase + p * 21 + 20];
            f2 iv = fpack(inv, inv);
            f2 r0 = fmul2(oacc[p][0], iv);
            f2 r1 = fmul2(oacc[p][1], iv);
            f2 r2 = fmul2(oacc[p][2], iv);
            f2 r3 = fmul2(oacc[p][3], iv);
            float4 oA, oB;
            funpack(r0, oA.x, oA.y); funpack(r1, oA.z, oA.w);
            funpack(r2, oB.x, oB.y); funpack(r3, oB.z, oB.w);
            float4* o4 = (float4*)out + bh_row0 + (size_t)(n0 + p) * HD4;
            o4[lane]     = oA;
            o4[lane + 8] = oB;
        }
    }
}

extern "C" void kernel_launch(void* const* d_in, const int* in_sizes, int n_in,
                              void* d_out, int out_size)
{
    const float* q  = (const float*)d_in[0];
    const float* k  = (const float*)d_in[1];
    const float* v  = (const float*)d_in[2];
    const float* pb = (const float*)d_in[3];
    const float* se = (const float*)d_in[4];
    float* out = (float*)d_out;

    const int blocks = NB * NH * (NSEQ / POS_PER_CTA);   // 128 * 32 = 4096
    dsqg_attn_kernel<<<blocks, 256>>>(q, k, v, pb, se, out);
}

// round 5
// speedup vs baseline: 1.3675x; 1.3675x over previous
#include <cuda_runtime.h>
#include <math.h>

#define JJN  20
#define NH   16
#define NSEQ 8192
#define NB   8
#define HD4  16          // float4 per 64-float row
#define GROUPS 32        // 256 threads / 8 lanes
#define POS_PER_CTA 128  // GROUPS * 4
#define EPOS 24          // float stride per position inside a group's e-block
#define EGRP 100         // float stride per group (4*24 + 4 pad; 100%32=4 banks)

// 80-slot schedule: pairs (t = row - n0, p = position-in-tile, j = offset idx),
// row-major over the 47 distinct rows of a P=4 tile.
__constant__ int c_T[80] = {
    2,1,1,0,0,0,-1,-1, -1,-1,-2,-2,-2,-2,-3,-3, -3,-3,-4,-4,-4,-4,-5,-5,
    -5,-5,-6,-6,-6,-6,-7,-7, -7,-8,-8,-8,-9,-9,-10,-10, -11,-11,-12,-12,-13,-13,-13,-14,
    -14,-15,-15,-16,-20,-21,-22,-23, -29,-30,-31,-32,-61,-62,-63,-64,
    -125,-126,-127,-128,-253,-254,-255,-256, -509,-510,-511,-512,-1021,-1022,-1023,-1024 };
__constant__ int c_P[80] = {
    3,2,3,1,2,3,0,1, 2,3,0,1,2,3,0,1, 2,3,0,1,2,3,0,1,
    2,3,0,1,2,3,0,1, 2,0,1,3,0,2,1,3, 0,2,1,3,0,2,3,1,
    2,0,1,0,3,2,1,0, 3,2,1,0,3,2,1,0,
    3,2,1,0,3,2,1,0, 3,2,1,0,3,2,1,0 };
__constant__ int c_J[80] = {
    0,0,1,0,1,2,0,1, 2,3,1,2,3,4,2,3, 4,5,3,4,5,6,4,5,
    6,7,5,6,7,8,6,7, 8,7,8,9,8,9,9,10, 9,10,10,11,10,11,12,11,
    12,11,12,12,13,13,13,13, 14,14,14,14,15,15,15,15,
    16,16,16,16,17,17,17,17, 18,18,18,18,19,19,19,19 };

// ---- packed f32x2 helpers ----
struct f2 { unsigned long long u; };
__device__ __forceinline__ f2 fpack(float x, float y) {
    f2 r; asm("mov.b64 %0, {%1,%2};" : "=l"(r.u) : "f"(x), "f"(y)); return r;
}
__device__ __forceinline__ f2 ffma2(f2 a, f2 b, f2 c) {
    f2 r; asm("fma.rn.f32x2 %0, %1, %2, %3;" : "=l"(r.u) : "l"(a.u), "l"(b.u), "l"(c.u)); return r;
}
__device__ __forceinline__ f2 fmul2(f2 a, f2 b) {
    f2 r; asm("mul.rn.f32x2 %0, %1, %2;" : "=l"(r.u) : "l"(a.u), "l"(b.u)); return r;
}
__device__ __forceinline__ void funpack(f2 a, float& x, float& y) {
    asm("mov.b64 {%0,%1}, %2;" : "=f"(x), "=f"(y) : "l"(a.u));
}

// Multi-value butterfly reduce-scatter: 8 lanes x 8 partials -> lane l (within
// its 8-lane group) returns the full 8-lane sum of partial slot l. 7 shuffles.
__device__ __forceinline__ float rscatter8(float part[8], int lane8) {
    {
        const bool hi = (lane8 & 4) != 0;
        #pragma unroll
        for (int i = 0; i < 4; i++) {
            float keep = hi ? part[i + 4] : part[i];
            float send = hi ? part[i]     : part[i + 4];
            float recv = __shfl_xor_sync(0xffffffffu, send, 4);
            part[i] = keep + recv;
        }
    }
    {
        const bool hi = (lane8 & 2) != 0;
        #pragma unroll
        for (int i = 0; i < 2; i++) {
            float keep = hi ? part[i + 2] : part[i];
            float send = hi ? part[i]     : part[i + 2];
            float recv = __shfl_xor_sync(0xffffffffu, send, 2);
            part[i] = keep + recv;
        }
    }
    {
        const bool hi = (lane8 & 1) != 0;
        float keep = hi ? part[1] : part[0];
        float send = hi ? part[0] : part[1];
        float recv = __shfl_xor_sync(0xffffffffu, send, 1);
        return keep + recv;
    }
}

__global__ __launch_bounds__(256, 2)
void dsqg_attn_kernel(const float* __restrict__ q,
                      const float* __restrict__ k,
                      const float* __restrict__ v,
                      const float* __restrict__ pos_bias,     // [J, H]
                      const float* __restrict__ scale_embed,  // [J, HD]
                      float* __restrict__ out)
{
    // compile-time copies of the schedule for the unrolled loop bodies
    const int SCH_T[80] = {
        2,1,1,0,0,0,-1,-1, -1,-1,-2,-2,-2,-2,-3,-3, -3,-3,-4,-4,-4,-4,-5,-5,
        -5,-5,-6,-6,-6,-6,-7,-7, -7,-8,-8,-8,-9,-9,-10,-10, -11,-11,-12,-12,-13,-13,-13,-14,
        -14,-15,-15,-16,-20,-21,-22,-23, -29,-30,-31,-32,-61,-62,-63,-64,
        -125,-126,-127,-128,-253,-254,-255,-256, -509,-510,-511,-512,-1021,-1022,-1023,-1024 };
    const int SCH_P[80] = {
        3,2,3,1,2,3,0,1, 2,3,0,1,2,3,0,1, 2,3,0,1,2,3,0,1,
        2,3,0,1,2,3,0,1, 2,0,1,3,0,2,1,3, 0,2,1,3,0,2,3,1,
        2,0,1,0,3,2,1,0, 3,2,1,0,3,2,1,0,
        3,2,1,0,3,2,1,0, 3,2,1,0,3,2,1,0 };
    const int SCH_J[80] = {
        0,0,1,0,1,2,0,1, 2,3,1,2,3,4,2,3, 4,5,3,4,5,6,4,5,
        6,7,5,6,7,8,6,7, 8,7,8,9,8,9,9,10, 9,10,10,11,10,11,12,11,
        12,11,12,12,13,13,13,13, 14,14,14,14,15,15,15,15,
        16,16,16,16,17,17,17,17, 18,18,18,18,19,19,19,19 };

    __shared__ float4 s_se[JJN][HD4];    // 5 KB
    __shared__ float  s_pb[JJN];
    __shared__ float  s_e[GROUPS * EGRP]; // 12.8 KB

    const int blocks_per_seq = NSEQ / POS_PER_CTA;          // 64
    const int bh   = blockIdx.x / blocks_per_seq;           // 0..127
    const int seq0 = (blockIdx.x % blocks_per_seq) * POS_PER_CTA;
    const int h    = bh % NH;

    for (int i = threadIdx.x; i < JJN * HD4; i += 256)
        ((float4*)s_se)[i] = ((const float4*)scale_embed)[i];
    if (threadIdx.x < JJN)
        s_pb[threadIdx.x] = pos_bias[threadIdx.x * NH + h];
    __syncthreads();

    const int gid   = threadIdx.x >> 3;    // 0..31
    const int lane8 = threadIdx.x & 7;     // 0..7
    const int n0    = seq0 + gid * 4;
    const int egbase = gid * EGRP;

    const size_t bh_row0 = (size_t)bh * NSEQ * HD4;
    const float4* __restrict__ kb4 = (const float4*)k + bh_row0;
    const float4* __restrict__ vb4 = (const float4*)v + bh_row0;
    const float4* __restrict__ qb4 = (const float4*)q + bh_row0;

    const float sc = 0.125f;

    // Load q (pre-scaled by 1/sqrt(64)); lane covers float4 slots {lane8, lane8+8}
    f2 qv[4][4];
    #pragma unroll
    for (int p = 0; p < 4; p++) {
        const float4* qr = qb4 + (size_t)(n0 + p) * HD4;
        float4 a = qr[lane8], b = qr[lane8 + 8];
        qv[p][0] = fpack(a.x * sc, a.y * sc);
        qv[p][1] = fpack(a.z * sc, a.w * sc);
        qv[p][2] = fpack(b.x * sc, b.y * sc);
        qv[p][3] = fpack(b.z * sc, b.w * sc);
    }

    float part[8];

    // ========== PHASE 0: qse[p][j] = sc*(q.se_j) + pb_j  (j-major) ==========
    {
        f2 s0, s1, s2, s3;
        #pragma unroll
        for (int i = 0; i < 80; i++) {
            const int j = i >> 2;
            if ((i & 3) == 0) {
                float4 sa = s_se[j][lane8], sb = s_se[j][lane8 + 8];
                s0 = fpack(sa.x, sa.y); s1 = fpack(sa.z, sa.w);
                s2 = fpack(sb.x, sb.y); s3 = fpack(sb.z, sb.w);
            }
            const int p = i & 3;
            f2 a = fmul2(qv[p][0], s0);
            a = ffma2(qv[p][1], s1, a);
            a = ffma2(qv[p][2], s2, a);
            a = ffma2(qv[p][3], s3, a);
            float x, y; funpack(a, x, y);
            part[i & 7] = x + y;
            if ((i & 7) == 7) {
                float red = rscatter8(part, lane8);
                const int pp = lane8 & 3;
                const int jj = 2 * (i >> 3) + (lane8 >> 2);
                s_e[egbase + pp * EPOS + jj] = red + s_pb[jj];
            }
        }
    }
    __syncwarp();

    // ========== PHASE 1: scores -> e (row-major k streaming) ==========
    {
        f2 k0, k1, k2, k3;
        #pragma unroll
        for (int i = 0; i < 80; i++) {
            if (i == 0 || SCH_T[i] != SCH_T[i - 1]) {
                int r = n0 + SCH_T[i];
                int rc = (r < 0) ? 0 : r;
                const float4* kr = kb4 + (size_t)rc * HD4;
                float4 ka = kr[lane8], kb2 = kr[lane8 + 8];
                k0 = fpack(ka.x, ka.y); k1 = fpack(ka.z, ka.w);
                k2 = fpack(kb2.x, kb2.y); k3 = fpack(kb2.z, kb2.w);
            }
            const int p = SCH_P[i];
            f2 a = fmul2(qv[p][0], k0);
            a = ffma2(qv[p][1], k1, a);
            a = ffma2(qv[p][2], k2, a);
            a = ffma2(qv[p][3], k3, a);
            float x, y; funpack(a, x, y);
            part[i & 7] = x + y;
            if ((i & 7) == 7) {
                float red = rscatter8(part, lane8);
                const int slot = (i - 7) + lane8;
                const int tt = c_T[slot];
                const int pp = c_P[slot];
                const int jj = c_J[slot];
                const int addr = egbase + pp * EPOS + jj;
                // No max-subtraction: scores are O(+-8), far below fp32 exp range.
                float e = (n0 + tt >= 0) ? __expf(red + s_e[addr]) : 0.f;
                s_e[addr] = e;
            }
        }
    }
    __syncwarp();

    // ========== denominators ==========
    if (lane8 < 4) {
        const float4* ep = (const float4*)&s_e[egbase + lane8 * EPOS];
        float4 a = ep[0], b = ep[1], c = ep[2], d = ep[3], e4 = ep[4];
        float s = a.x + a.y + a.z + a.w + b.x + b.y + b.z + b.w
                + c.x + c.y + c.z + c.w + d.x + d.y + d.z + d.w
                + e4.x + e4.y + e4.z + e4.w;
        s_e[egbase + lane8 * EPOS + 20] = 1.0f / fmaxf(s, 1e-30f);
    }
    __syncwarp();

    // ========== PHASE 2: out = (sum_j e * v) * inv ==========
    {
        f2 oacc[4][4];
        #pragma unroll
        for (int p = 0; p < 4; p++)
            #pragma unroll
            for (int c = 0; c < 4; c++) oacc[p][c] = fpack(0.f, 0.f);

        f2 v0, v1, v2, v3;
        #pragma unroll
        for (int i = 0; i < 80; i++) {
            if (i == 0 || SCH_T[i] != SCH_T[i - 1]) {
                int r = n0 + SCH_T[i];
                int rc = (r < 0) ? 0 : r;   // e == 0 when masked, clamp safe
                const float4* vr = vb4 + (size_t)rc * HD4;
                float4 va = vr[lane8], vb2 = vr[lane8 + 8];
                v0 = fpack(va.x, va.y); v1 = fpack(va.z, va.w);
                v2 = fpack(vb2.x, vb2.y); v3 = fpack(vb2.z, vb2.w);
            }
            const int p = SCH_P[i];
            const float e = s_e[egbase + p * EPOS + SCH_J[i]];
            f2 e2 = fpack(e, e);
            oacc[p][0] = ffma2(e2, v0, oacc[p][0]);
            oacc[p][1] = ffma2(e2, v1, oacc[p][1]);
            oacc[p][2] = ffma2(e2, v2, oacc[p][2]);
            oacc[p][3] = ffma2(e2, v3, oacc[p][3]);
        }

        #pragma unroll
        for (int p = 0; p < 4; p++) {
            const float inv = s_e[egbase + p * EPOS + 20];
            f2 iv = fpack(inv, inv);
            f2 r0 = fmul2(oacc[p][0], iv);
            f2 r1 = fmul2(oacc[p][1], iv);
            f2 r2 = fmul2(oacc[p][2], iv);
            f2 r3 = fmul2(oacc[p][3], iv);
            float4 oA, oB;
            funpack(r0, oA.x, oA.y); funpack(r1, oA.z, oA.w);
            funpack(r2, oB.x, oB.y); funpack(r3, oB.z, oB.w);
            float4* o4 = (float4*)out + bh_row0 + (size_t)(n0 + p) * HD4;
            o4[lane8]     = oA;
            o4[lane8 + 8] = oB;
        }
    }
}

extern "C" void kernel_launch(void* const* d_in, const int* in_sizes, int n_in,
                              void* d_out, int out_size)
{
    const float* q  = (const float*)d_in[0];
    const float* k  = (const float*)d_in[1];
    const float* v  = (const float*)d_in[2];
    const float* pb = (const float*)d_in[3];
    const float* se = (const float*)d_in[4];
    float* out = (float*)d_out;

    const int blocks = NB * NH * (NSEQ / POS_PER_CTA);   // 128 * 64 = 8192
    dsqg_attn_kernel<<<blocks, 256>>>(q, k, v, pb, se, out);
}